// round 14
// baseline (speedup 1.0000x reference)
#include <cuda_runtime.h>
#include <cuda_fp16.h>
#include <stdint.h>

#define NNODES_MAX 100000
#define NROWS_PAD  100096     // padded for 128-row GEMM tiles
#define NEDGES_MAX 3200000
#define F_IN 128
#define F4 32            // float4s per feature row
#define H2_ROW 32        // uint2 (4 halves) per feature row
#define SCAN_BLK 1024

// ---- scratch (static __device__ globals; allocation-free, zero-init) ----
__device__ int    g_deg[NNODES_MAX];       // in-degree counts (stable after count)
__device__ int    g_cur[NNODES_MAX];       // permute placement cursors
__device__ int    g_off[NNODES_MAX];       // CSR offsets
__device__ int    g_bsum[128];
__device__ float  g_dinv[NNODES_MAX];
__device__ int    g_edge[NEDGES_MAX];                    // src per edge, dst-sorted
__device__ uint2  g_xh[(size_t)NNODES_MAX * H2_ROW];     // fp16(x * dinv[row])
__device__ uint2  g_acch[(size_t)NROWS_PAD * H2_ROW];    // fp16 aggregated features
__device__ __half g_wh[128 * 128];                       // combined [W_mu|W_ls] fp16, [k][j]
__device__ float  g_bias[128];                           // combined bias

// ---------------------------------------------------------------------------
// K0: zero deg + cursors, convert W to fp16, bias (independent work, merged)
// ---------------------------------------------------------------------------
__global__ void k_zero_wconv(int n,
                             const float* __restrict__ Wmu, const float* __restrict__ bmu,
                             const float* __restrict__ Wls, const float* __restrict__ bls) {
    int i = blockIdx.x * blockDim.x + threadIdx.x;
    if (i < n) { g_deg[i] = 0; g_cur[i] = 0; }
    if (i < 128 * 128) {
        int k = i >> 7, j = i & 127;
        float w = (j < 64) ? Wmu[k * 64 + j] : Wls[k * 64 + (j - 64)];
        g_wh[i] = __float2half_rn(w);
    }
    if (i < 128) g_bias[i] = (i < 64) ? bmu[i] : bls[i - 64];
}

// ---------------------------------------------------------------------------
// K1: in-degree count
// ---------------------------------------------------------------------------
__global__ void k_count(const int* __restrict__ col, int E) {
    int i = blockIdx.x * blockDim.x + threadIdx.x;
    int base = i * 4;
    if (base + 3 < E) {
        int4 c = *reinterpret_cast<const int4*>(col + base);
        atomicAdd(&g_deg[c.x], 1);
        atomicAdd(&g_deg[c.y], 1);
        atomicAdd(&g_deg[c.z], 1);
        atomicAdd(&g_deg[c.w], 1);
    } else if (base < E) {
        for (int e = base; e < E; ++e) atomicAdd(&g_deg[col[e]], 1);
    }
}

// ---------------------------------------------------------------------------
// K2: per-block exclusive scan of indeg -> g_off (block-local), totals -> g_bsum
// ---------------------------------------------------------------------------
__global__ void k_scan_part(int n) {
    __shared__ int s[SCAN_BLK];
    int tid = threadIdx.x;
    int v = blockIdx.x * SCAN_BLK + tid;
    int val = (v < n) ? g_deg[v] : 0;
    s[tid] = val;
    __syncthreads();
    #pragma unroll
    for (int off = 1; off < SCAN_BLK; off <<= 1) {
        int t = (tid >= off) ? s[tid - off] : 0;
        __syncthreads();
        s[tid] += t;
        __syncthreads();
    }
    if (v < n) g_off[v] = s[tid] - val;
    if (tid == SCAN_BLK - 1) g_bsum[blockIdx.x] = s[tid];
}

// ---------------------------------------------------------------------------
// K3: off-fixup + dinv. One thread per node; per-block redundant g_bsum reduce.
// Does NOT touch g_deg (counts stay live for prescale/gather).
// ---------------------------------------------------------------------------
__global__ void k_fix(int n) {
    __shared__ int sred[128];
    __shared__ int sbase;
    int tid = threadIdx.x;
    int grp = (blockIdx.x * 256) >> 10;

    if (tid < 128) sred[tid] = (tid < grp) ? g_bsum[tid] : 0;
    __syncthreads();
    if (tid < 64) sred[tid] += sred[tid + 64];
    __syncthreads();
    if (tid < 32) {
        int vv = sred[tid] + sred[tid + 32];
        #pragma unroll
        for (int o = 16; o > 0; o >>= 1) vv += __shfl_down_sync(0xffffffffu, vv, o);
        if (tid == 0) sbase = vv;
    }
    __syncthreads();

    int v = blockIdx.x * 256 + tid;
    if (v < n) {
        g_off[v] += sbase;
        g_dinv[v] = rsqrtf((float)(g_deg[v] + 1));
    }
}

// ---------------------------------------------------------------------------
// K4a (side stream): prescale x into fp16 (dinv computed locally from g_deg)
// ---------------------------------------------------------------------------
__global__ void k_prescale(const float* __restrict__ x, int n) {
    int idx = blockIdx.x * blockDim.x + threadIdx.x;
    if (idx >= n * F4) return;
    int v = idx >> 5;
    float dv = rsqrtf((float)(g_deg[v] + 1));
    float4 xv = reinterpret_cast<const float4*>(x)[idx];
    __half2 h0 = __floats2half2_rn(xv.x * dv, xv.y * dv);
    __half2 h1 = __floats2half2_rn(xv.z * dv, xv.w * dv);
    uint2 o;
    o.x = *reinterpret_cast<unsigned*>(&h0);
    o.y = *reinterpret_cast<unsigned*>(&h1);
    g_xh[idx] = o;
}

// ---------------------------------------------------------------------------
// K4b (main stream): permute edges into dst-sorted order (cursors in g_cur)
// ---------------------------------------------------------------------------
__global__ void k_permute(const int* __restrict__ rowi,
                          const int* __restrict__ coli, int E) {
    int i = blockIdx.x * blockDim.x + threadIdx.x;
    int base = i * 4;
    if (base + 3 < E) {
        int4 s4 = *reinterpret_cast<const int4*>(rowi + base);
        int4 d4 = *reinterpret_cast<const int4*>(coli + base);
        g_edge[g_off[d4.x] + atomicAdd(&g_cur[d4.x], 1)] = s4.x;
        g_edge[g_off[d4.y] + atomicAdd(&g_cur[d4.y], 1)] = s4.y;
        g_edge[g_off[d4.z] + atomicAdd(&g_cur[d4.z], 1)] = s4.z;
        g_edge[g_off[d4.w] + atomicAdd(&g_cur[d4.w], 1)] = s4.w;
    } else if (base < E) {
        for (int e = base; e < E; ++e) {
            int s = rowi[e], d = coli[e];
            g_edge[g_off[d] + atomicAdd(&g_cur[d], 1)] = s;
        }
    }
}

// ---------------------------------------------------------------------------
// K5: gather-aggregate for node range [v0, v0+vcnt), MLP=4.
// One warp per dst node; each lane owns 4 features.
// ---------------------------------------------------------------------------
__global__ void k_gather(int v0, int vcnt) {
    int gwarp = (blockIdx.x * blockDim.x + threadIdx.x) >> 5;
    int lane  = threadIdx.x & 31;
    if (gwarp >= vcnt) return;
    int v = v0 + gwarp;

    float dv_dst = g_dinv[v];
    int offs = g_off[v];
    int cnt  = g_deg[v];

    float ax, ay, az, aw;
    {
        uint2 h = __ldg(&g_xh[(size_t)v * H2_ROW + lane]);
        float2 f0 = __half22float2(*reinterpret_cast<__half2*>(&h.x));
        float2 f1 = __half22float2(*reinterpret_cast<__half2*>(&h.y));
        ax = f0.x; ay = f0.y; az = f1.x; aw = f1.y;
    }

    for (int base = 0; base < cnt; base += 32) {
        int m = min(32, cnt - base);
        int s = 0;
        if (base + lane < cnt) s = __ldg(&g_edge[offs + base + lane]);

        int e = 0;
        for (; e + 3 < m; e += 4) {
            int s0 = __shfl_sync(0xffffffffu, s, e);
            int s1 = __shfl_sync(0xffffffffu, s, e + 1);
            int s2 = __shfl_sync(0xffffffffu, s, e + 2);
            int s3 = __shfl_sync(0xffffffffu, s, e + 3);
            uint2 h0 = __ldg(&g_xh[(size_t)s0 * H2_ROW + lane]);
            uint2 h1 = __ldg(&g_xh[(size_t)s1 * H2_ROW + lane]);
            uint2 h2 = __ldg(&g_xh[(size_t)s2 * H2_ROW + lane]);
            uint2 h3 = __ldg(&g_xh[(size_t)s3 * H2_ROW + lane]);
            float2 a, b;
            a = __half22float2(*reinterpret_cast<__half2*>(&h0.x));
            b = __half22float2(*reinterpret_cast<__half2*>(&h0.y));
            ax += a.x; ay += a.y; az += b.x; aw += b.y;
            a = __half22float2(*reinterpret_cast<__half2*>(&h1.x));
            b = __half22float2(*reinterpret_cast<__half2*>(&h1.y));
            ax += a.x; ay += a.y; az += b.x; aw += b.y;
            a = __half22float2(*reinterpret_cast<__half2*>(&h2.x));
            b = __half22float2(*reinterpret_cast<__half2*>(&h2.y));
            ax += a.x; ay += a.y; az += b.x; aw += b.y;
            a = __half22float2(*reinterpret_cast<__half2*>(&h3.x));
            b = __half22float2(*reinterpret_cast<__half2*>(&h3.y));
            ax += a.x; ay += a.y; az += b.x; aw += b.y;
        }
        for (; e < m; ++e) {
            int s0 = __shfl_sync(0xffffffffu, s, e);
            uint2 h0 = __ldg(&g_xh[(size_t)s0 * H2_ROW + lane]);
            float2 a = __half22float2(*reinterpret_cast<__half2*>(&h0.x));
            float2 b = __half22float2(*reinterpret_cast<__half2*>(&h0.y));
            ax += a.x; ay += a.y; az += b.x; aw += b.y;
        }
    }

    __half2 h0 = __floats2half2_rn(ax * dv_dst, ay * dv_dst);
    __half2 h1 = __floats2half2_rn(az * dv_dst, aw * dv_dst);
    uint2 o;
    o.x = *reinterpret_cast<unsigned*>(&h0);
    o.y = *reinterpret_cast<unsigned*>(&h1);
    g_acch[(size_t)v * H2_ROW + lane] = o;
}

// ---------------------------------------------------------------------------
// K6: HMMA GEMM over row range starting at row0 (tile-aligned).
//   out = g_acch @ g_wh + g_bias   (fp16 in, fp32 accumulate)
// ---------------------------------------------------------------------------
__global__ void k_gemm_hmma(float* __restrict__ out, int row0, int n) {
    extern __shared__ __half sm[];
    __half* As = sm;                         // 128*136
    __half* Ws = sm + 128 * 136;             // 128*136
    float*  bs = (float*)(sm + 2 * 128 * 136);

    int tid = threadIdx.x;
    int rowbase = row0 + blockIdx.x * 128;

    {
        const uint4* src = reinterpret_cast<const uint4*>(g_wh);
        for (int t = tid; t < 128 * 16; t += 256) {
            int r = t >> 4, c = t & 15;
            *reinterpret_cast<uint4*>(Ws + r * 136 + c * 8) = src[r * 16 + c];
        }
    }
    {
        const uint4* src = reinterpret_cast<const uint4*>(g_acch);
        for (int t = tid; t < 128 * 16; t += 256) {
            int r = t >> 4, c = t & 15;
            *reinterpret_cast<uint4*>(As + r * 136 + c * 8) =
                src[(size_t)(rowbase + r) * 16 + c];
        }
    }
    if (tid < 128) bs[tid] = g_bias[tid];
    __syncthreads();

    int warp = tid >> 5, lane = tid & 31;
    int m0 = warp * 16;

    float c[16][4];
    #pragma unroll
    for (int t = 0; t < 16; ++t) { c[t][0] = c[t][1] = c[t][2] = c[t][3] = 0.f; }

    uint32_t a_base = (uint32_t)__cvta_generic_to_shared(As);
    uint32_t b_base = (uint32_t)__cvta_generic_to_shared(Ws);

    #pragma unroll
    for (int kk = 0; kk < 8; ++kk) {
        int k0 = kk * 16;
        uint32_t a0, a1, a2, a3;
        {
            int r   = m0 + (lane & 15);
            int col = k0 + 8 * (lane >> 4);
            uint32_t addr = a_base + (uint32_t)(r * 136 + col) * 2u;
            asm volatile(
                "ldmatrix.sync.aligned.m8n8.x4.shared.b16 {%0,%1,%2,%3}, [%4];"
                : "=r"(a0), "=r"(a1), "=r"(a2), "=r"(a3) : "r"(addr));
        }
        #pragma unroll
        for (int nt = 0; nt < 16; ++nt) {
            uint32_t b0, b1;
            int r = k0 + (lane & 15);
            uint32_t addr = b_base + (uint32_t)(r * 136 + nt * 8) * 2u;
            asm volatile(
                "ldmatrix.sync.aligned.m8n8.x2.trans.shared.b16 {%0,%1}, [%2];"
                : "=r"(b0), "=r"(b1) : "r"(addr));
            asm volatile(
                "mma.sync.aligned.m16n8k16.row.col.f32.f16.f16.f32 "
                "{%0,%1,%2,%3}, {%4,%5,%6,%7}, {%8,%9}, {%0,%1,%2,%3};"
                : "+f"(c[nt][0]), "+f"(c[nt][1]), "+f"(c[nt][2]), "+f"(c[nt][3])
                : "r"(a0), "r"(a1), "r"(a2), "r"(a3), "r"(b0), "r"(b1));
        }
    }

    int g  = lane >> 2;
    int t4 = lane & 3;
    float* outm = out;
    float* outl = out + (size_t)n * 64;
    #pragma unroll
    for (int nt = 0; nt < 16; ++nt) {
        int col = nt * 8 + t4 * 2;
        float bi0 = bs[col], bi1 = bs[col + 1];
        int v0 = rowbase + m0 + g;
        int v1 = v0 + 8;
        if (col < 64) {
            if (v0 < n)
                *reinterpret_cast<float2*>(outm + (size_t)v0 * 64 + col) =
                    make_float2(c[nt][0] + bi0, c[nt][1] + bi1);
            if (v1 < n)
                *reinterpret_cast<float2*>(outm + (size_t)v1 * 64 + col) =
                    make_float2(c[nt][2] + bi0, c[nt][3] + bi1);
        } else {
            int cl = col - 64;
            if (v0 < n)
                *reinterpret_cast<float2*>(outl + (size_t)v0 * 64 + cl) =
                    make_float2(c[nt][0] + bi0, c[nt][1] + bi1);
            if (v1 < n)
                *reinterpret_cast<float2*>(outl + (size_t)v1 * 64 + cl) =
                    make_float2(c[nt][2] + bi0, c[nt][3] + bi1);
        }
    }
}

// ---------------------------------------------------------------------------
// launch: prescale overlapped with scan/fix/permute; gather/gemm pipelined
// in 2 chunks so gemm(chunk1) hides under gather(chunk2).
// ---------------------------------------------------------------------------
extern "C" void kernel_launch(void* const* d_in, const int* in_sizes, int n_in,
                              void* d_out, int out_size) {
    const float* x   = (const float*)d_in[0];
    const int*   ei  = (const int*)d_in[1];
    const float* Wmu = (const float*)d_in[2];
    const float* bmu = (const float*)d_in[3];
    const float* Wls = (const float*)d_in[4];
    const float* bls = (const float*)d_in[5];

    int n = in_sizes[0] / F_IN;     // 100000
    int E = in_sizes[1] / 2;        // 3200000
    const int* rowi = ei;           // edge_index[0] (src)
    const int* coli = ei + E;       // edge_index[1] (dst)

    int nb = (n + SCAN_BLK - 1) / SCAN_BLK;   // 98

    cudaStream_t s2;
    cudaStreamCreateWithFlags(&s2, cudaStreamNonBlocking);
    cudaEvent_t evFork, evJoin, evG1, evGemm1;
    cudaEventCreateWithFlags(&evFork, cudaEventDisableTiming);
    cudaEventCreateWithFlags(&evJoin, cudaEventDisableTiming);
    cudaEventCreateWithFlags(&evG1,   cudaEventDisableTiming);
    cudaEventCreateWithFlags(&evGemm1, cudaEventDisableTiming);

    int zw_grid = ((n > 128 * 128 ? n : 128 * 128) + 255) / 256;
    k_zero_wconv<<<zw_grid, 256>>>(n, Wmu, bmu, Wls, bls);
    k_count<<<((E + 3) / 4 + 255) / 256, 256>>>(coli, E);

    // fork: prescale on s2 (needs only degree counts)
    cudaEventRecord(evFork, 0);
    cudaStreamWaitEvent(s2, evFork, 0);
    k_prescale<<<(n * F4 + 255) / 256, 256, 0, s2>>>(x, n);
    cudaEventRecord(evJoin, s2);

    // main: scan -> fix -> permute
    k_scan_part<<<nb, SCAN_BLK>>>(n);
    k_fix<<<(n + 255) / 256, 256>>>(n);
    k_permute<<<((E + 3) / 4 + 255) / 256, 256>>>(rowi, coli, E);
    cudaStreamWaitEvent(0, evJoin, 0);

    int smem_bytes = 2 * 128 * 136 * (int)sizeof(__half) + 128 * (int)sizeof(float);
    cudaFuncSetAttribute(k_gemm_hmma, cudaFuncAttributeMaxDynamicSharedMemorySize,
                         smem_bytes);

    // chunk split, aligned to 128-row gemm tiles
    int half = ((n / 2 + 127) / 128) * 128;          // 50048
    int rest = n - half;                              // 49952

    // gather chunk 1 (main)
    k_gather<<<(half * 32 + 255) / 256, 256>>>(0, half);
    cudaEventRecord(evG1, 0);

    // gemm chunk 1 on s2, concurrent with gather chunk 2 on main
    cudaStreamWaitEvent(s2, evG1, 0);
    k_gemm_hmma<<<half / 128, 256, smem_bytes, s2>>>((float*)d_out, 0, n);
    cudaEventRecord(evGemm1, s2);

    k_gather<<<(rest * 32 + 255) / 256, 256>>>(half, rest);
    k_gemm_hmma<<<(rest + 127) / 128, 256, smem_bytes>>>((float*)d_out, half, n);

    // join gemm1 back into origin stream before capture ends
    cudaStreamWaitEvent(0, evGemm1, 0);

    cudaEventDestroy(evFork);
    cudaEventDestroy(evJoin);
    cudaEventDestroy(evG1);
    cudaEventDestroy(evGemm1);
    cudaStreamDestroy(s2);
}

// round 15
// speedup vs baseline: 1.0343x; 1.0343x over previous
#include <cuda_runtime.h>
#include <cuda_fp16.h>
#include <stdint.h>

#define NNODES_MAX 100000
#define NROWS_PAD  100096     // padded for 128-row GEMM tiles
#define NEDGES_MAX 3200000
#define F_IN 128
#define F4 32            // float4s per feature row
#define H2_ROW 32        // uint2 (4 halves) per feature row
#define SCAN_BLK 1024

// ---- scratch (static __device__ globals; allocation-free, zero-init) ----
__device__ int    g_deg[NNODES_MAX];       // in-degree counts (stable after count)
__device__ int    g_cur[NNODES_MAX];       // permute placement cursors
__device__ int    g_off[NNODES_MAX];       // CSR offsets
__device__ int    g_pub[128];              // lookback publications (0=not ready, total+1)
__device__ float  g_dinv[NNODES_MAX];
__device__ int    g_edge[NEDGES_MAX];                    // src per edge, dst-sorted
__device__ uint2  g_xh[(size_t)NNODES_MAX * H2_ROW];     // fp16(x * dinv[row])
__device__ uint2  g_acch[(size_t)NROWS_PAD * H2_ROW];    // fp16 aggregated features
__device__ __half g_wh[128 * 128];                       // combined [W_mu|W_ls] fp16, [k][j]
__device__ float  g_bias[128];                           // combined bias

// ---------------------------------------------------------------------------
// K0: zero deg + cursors + lookback flags, convert W to fp16, bias
// ---------------------------------------------------------------------------
__global__ void k_zero_wconv(int n,
                             const float* __restrict__ Wmu, const float* __restrict__ bmu,
                             const float* __restrict__ Wls, const float* __restrict__ bls) {
    int i = blockIdx.x * blockDim.x + threadIdx.x;
    if (i < n) { g_deg[i] = 0; g_cur[i] = 0; }
    if (i < 128) g_pub[i] = 0;
    if (i < 128 * 128) {
        int k = i >> 7, j = i & 127;
        float w = (j < 64) ? Wmu[k * 64 + j] : Wls[k * 64 + (j - 64)];
        g_wh[i] = __float2half_rn(w);
    }
    if (i < 128) g_bias[i] = (i < 64) ? bmu[i] : bls[i - 64];
}

// ---------------------------------------------------------------------------
// K1: in-degree count
// ---------------------------------------------------------------------------
__global__ void k_count(const int* __restrict__ col, int E) {
    int i = blockIdx.x * blockDim.x + threadIdx.x;
    int base = i * 4;
    if (base + 3 < E) {
        int4 c = *reinterpret_cast<const int4*>(col + base);
        atomicAdd(&g_deg[c.x], 1);
        atomicAdd(&g_deg[c.y], 1);
        atomicAdd(&g_deg[c.z], 1);
        atomicAdd(&g_deg[c.w], 1);
    } else if (base < E) {
        for (int e = base; e < E; ++e) atomicAdd(&g_deg[col[e]], 1);
    }
}

// ---------------------------------------------------------------------------
// K2: single-pass scan with decoupled lookback.
//   g_off[v] = global exclusive prefix of indeg; g_dinv[v] = rsqrt(indeg+1)
// 98 blocks, all co-resident in wave 1 -> parallel-poll lookback is safe.
// ---------------------------------------------------------------------------
__global__ void k_scan(int n) {
    __shared__ int s[SCAN_BLK];
    int tid = threadIdx.x, b = blockIdx.x;
    int v = b * SCAN_BLK + tid;
    int val = (v < n) ? g_deg[v] : 0;
    s[tid] = val;
    __syncthreads();
    #pragma unroll
    for (int off = 1; off < SCAN_BLK; off <<= 1) {
        int t = (tid >= off) ? s[tid - off] : 0;
        __syncthreads();
        s[tid] += t;
        __syncthreads();
    }
    int incl = s[tid];                       // inclusive prefix within block

    // publish this block's total (value+1; 0 means not ready)
    if (tid == SCAN_BLK - 1) atomicExch(&g_pub[b], incl + 1);

    // parallel lookback: thread tid < b polls predecessor tid's aggregate
    int part = 0;
    if (tid < b) {
        int p;
        do { p = atomicAdd(&g_pub[tid], 0); } while (p == 0);
        part = p - 1;
    }
    __syncthreads();                         // everyone done reading s as scan
    s[tid] = part;
    __syncthreads();
    #pragma unroll
    for (int o = SCAN_BLK / 2; o > 0; o >>= 1) {
        if (tid < o) s[tid] += s[tid + o];
        __syncthreads();
    }
    int base = s[0];

    if (v < n) {
        g_off[v]  = base + incl - val;       // global exclusive prefix
        g_dinv[v] = rsqrtf((float)(val + 1));
    }
}

// ---------------------------------------------------------------------------
// K3a (side stream): prescale x into fp16 (dinv computed locally from g_deg)
// ---------------------------------------------------------------------------
__global__ void k_prescale(const float* __restrict__ x, int n) {
    int idx = blockIdx.x * blockDim.x + threadIdx.x;
    if (idx >= n * F4) return;
    int v = idx >> 5;
    float dv = rsqrtf((float)(g_deg[v] + 1));
    float4 xv = reinterpret_cast<const float4*>(x)[idx];
    __half2 h0 = __floats2half2_rn(xv.x * dv, xv.y * dv);
    __half2 h1 = __floats2half2_rn(xv.z * dv, xv.w * dv);
    uint2 o;
    o.x = *reinterpret_cast<unsigned*>(&h0);
    o.y = *reinterpret_cast<unsigned*>(&h1);
    g_xh[idx] = o;
}

// ---------------------------------------------------------------------------
// K3b (main stream): permute edges into dst-sorted order (cursors in g_cur)
// ---------------------------------------------------------------------------
__global__ void k_permute(const int* __restrict__ rowi,
                          const int* __restrict__ coli, int E) {
    int i = blockIdx.x * blockDim.x + threadIdx.x;
    int base = i * 4;
    if (base + 3 < E) {
        int4 s4 = *reinterpret_cast<const int4*>(rowi + base);
        int4 d4 = *reinterpret_cast<const int4*>(coli + base);
        g_edge[g_off[d4.x] + atomicAdd(&g_cur[d4.x], 1)] = s4.x;
        g_edge[g_off[d4.y] + atomicAdd(&g_cur[d4.y], 1)] = s4.y;
        g_edge[g_off[d4.z] + atomicAdd(&g_cur[d4.z], 1)] = s4.z;
        g_edge[g_off[d4.w] + atomicAdd(&g_cur[d4.w], 1)] = s4.w;
    } else if (base < E) {
        for (int e = base; e < E; ++e) {
            int s = rowi[e], d = coli[e];
            g_edge[g_off[d] + atomicAdd(&g_cur[d], 1)] = s;
        }
    }
}

// ---------------------------------------------------------------------------
// K4: gather-aggregate (fp16 rows, fp32 accumulate), fp16 output, MLP=4.
// One warp per dst node; each lane owns 4 features.
// ---------------------------------------------------------------------------
__global__ void k_gather(int n) {
    int gwarp = (blockIdx.x * blockDim.x + threadIdx.x) >> 5;
    int lane  = threadIdx.x & 31;
    if (gwarp >= n) return;
    int v = gwarp;

    float dv_dst = g_dinv[v];
    int offs = g_off[v];
    int cnt  = g_deg[v];

    float ax, ay, az, aw;
    {
        uint2 h = __ldg(&g_xh[(size_t)v * H2_ROW + lane]);
        float2 f0 = __half22float2(*reinterpret_cast<__half2*>(&h.x));
        float2 f1 = __half22float2(*reinterpret_cast<__half2*>(&h.y));
        ax = f0.x; ay = f0.y; az = f1.x; aw = f1.y;
    }

    for (int base = 0; base < cnt; base += 32) {
        int m = min(32, cnt - base);
        int s = 0;
        if (base + lane < cnt) s = __ldg(&g_edge[offs + base + lane]);

        int e = 0;
        for (; e + 3 < m; e += 4) {
            int s0 = __shfl_sync(0xffffffffu, s, e);
            int s1 = __shfl_sync(0xffffffffu, s, e + 1);
            int s2 = __shfl_sync(0xffffffffu, s, e + 2);
            int s3 = __shfl_sync(0xffffffffu, s, e + 3);
            uint2 h0 = __ldg(&g_xh[(size_t)s0 * H2_ROW + lane]);
            uint2 h1 = __ldg(&g_xh[(size_t)s1 * H2_ROW + lane]);
            uint2 h2 = __ldg(&g_xh[(size_t)s2 * H2_ROW + lane]);
            uint2 h3 = __ldg(&g_xh[(size_t)s3 * H2_ROW + lane]);
            float2 a, b;
            a = __half22float2(*reinterpret_cast<__half2*>(&h0.x));
            b = __half22float2(*reinterpret_cast<__half2*>(&h0.y));
            ax += a.x; ay += a.y; az += b.x; aw += b.y;
            a = __half22float2(*reinterpret_cast<__half2*>(&h1.x));
            b = __half22float2(*reinterpret_cast<__half2*>(&h1.y));
            ax += a.x; ay += a.y; az += b.x; aw += b.y;
            a = __half22float2(*reinterpret_cast<__half2*>(&h2.x));
            b = __half22float2(*reinterpret_cast<__half2*>(&h2.y));
            ax += a.x; ay += a.y; az += b.x; aw += b.y;
            a = __half22float2(*reinterpret_cast<__half2*>(&h3.x));
            b = __half22float2(*reinterpret_cast<__half2*>(&h3.y));
            ax += a.x; ay += a.y; az += b.x; aw += b.y;
        }
        for (; e < m; ++e) {
            int s0 = __shfl_sync(0xffffffffu, s, e);
            uint2 h0 = __ldg(&g_xh[(size_t)s0 * H2_ROW + lane]);
            float2 a = __half22float2(*reinterpret_cast<__half2*>(&h0.x));
            float2 b = __half22float2(*reinterpret_cast<__half2*>(&h0.y));
            ax += a.x; ay += a.y; az += b.x; aw += b.y;
        }
    }

    __half2 h0 = __floats2half2_rn(ax * dv_dst, ay * dv_dst);
    __half2 h1 = __floats2half2_rn(az * dv_dst, aw * dv_dst);
    uint2 o;
    o.x = *reinterpret_cast<unsigned*>(&h0);
    o.y = *reinterpret_cast<unsigned*>(&h1);
    g_acch[(size_t)v * H2_ROW + lane] = o;
}

// ---------------------------------------------------------------------------
// K5: HMMA GEMM:  out = g_acch @ g_wh + g_bias   (fp16 in, fp32 accumulate)
// ---------------------------------------------------------------------------
__global__ void k_gemm_hmma(float* __restrict__ out, int n) {
    extern __shared__ __half sm[];
    __half* As = sm;                         // 128*136
    __half* Ws = sm + 128 * 136;             // 128*136
    float*  bs = (float*)(sm + 2 * 128 * 136);

    int tid = threadIdx.x;
    int rowbase = blockIdx.x * 128;

    {
        const uint4* src = reinterpret_cast<const uint4*>(g_wh);
        for (int t = tid; t < 128 * 16; t += 256) {
            int r = t >> 4, c = t & 15;
            *reinterpret_cast<uint4*>(Ws + r * 136 + c * 8) = src[r * 16 + c];
        }
    }
    {
        const uint4* src = reinterpret_cast<const uint4*>(g_acch);
        for (int t = tid; t < 128 * 16; t += 256) {
            int r = t >> 4, c = t & 15;
            *reinterpret_cast<uint4*>(As + r * 136 + c * 8) =
                src[(size_t)(rowbase + r) * 16 + c];
        }
    }
    if (tid < 128) bs[tid] = g_bias[tid];
    __syncthreads();

    int warp = tid >> 5, lane = tid & 31;
    int m0 = warp * 16;

    float c[16][4];
    #pragma unroll
    for (int t = 0; t < 16; ++t) { c[t][0] = c[t][1] = c[t][2] = c[t][3] = 0.f; }

    uint32_t a_base = (uint32_t)__cvta_generic_to_shared(As);
    uint32_t b_base = (uint32_t)__cvta_generic_to_shared(Ws);

    #pragma unroll
    for (int kk = 0; kk < 8; ++kk) {
        int k0 = kk * 16;
        uint32_t a0, a1, a2, a3;
        {
            int r   = m0 + (lane & 15);
            int col = k0 + 8 * (lane >> 4);
            uint32_t addr = a_base + (uint32_t)(r * 136 + col) * 2u;
            asm volatile(
                "ldmatrix.sync.aligned.m8n8.x4.shared.b16 {%0,%1,%2,%3}, [%4];"
                : "=r"(a0), "=r"(a1), "=r"(a2), "=r"(a3) : "r"(addr));
        }
        #pragma unroll
        for (int nt = 0; nt < 16; ++nt) {
            uint32_t b0, b1;
            int r = k0 + (lane & 15);
            uint32_t addr = b_base + (uint32_t)(r * 136 + nt * 8) * 2u;
            asm volatile(
                "ldmatrix.sync.aligned.m8n8.x2.trans.shared.b16 {%0,%1}, [%2];"
                : "=r"(b0), "=r"(b1) : "r"(addr));
            asm volatile(
                "mma.sync.aligned.m16n8k16.row.col.f32.f16.f16.f32 "
                "{%0,%1,%2,%3}, {%4,%5,%6,%7}, {%8,%9}, {%0,%1,%2,%3};"
                : "+f"(c[nt][0]), "+f"(c[nt][1]), "+f"(c[nt][2]), "+f"(c[nt][3])
                : "r"(a0), "r"(a1), "r"(a2), "r"(a3), "r"(b0), "r"(b1));
        }
    }

    int g  = lane >> 2;
    int t4 = lane & 3;
    float* outm = out;
    float* outl = out + (size_t)n * 64;
    #pragma unroll
    for (int nt = 0; nt < 16; ++nt) {
        int col = nt * 8 + t4 * 2;
        float bi0 = bs[col], bi1 = bs[col + 1];
        int v0 = rowbase + m0 + g;
        int v1 = v0 + 8;
        if (col < 64) {
            if (v0 < n)
                *reinterpret_cast<float2*>(outm + (size_t)v0 * 64 + col) =
                    make_float2(c[nt][0] + bi0, c[nt][1] + bi1);
            if (v1 < n)
                *reinterpret_cast<float2*>(outm + (size_t)v1 * 64 + col) =
                    make_float2(c[nt][2] + bi0, c[nt][3] + bi1);
        } else {
            int cl = col - 64;
            if (v0 < n)
                *reinterpret_cast<float2*>(outl + (size_t)v0 * 64 + cl) =
                    make_float2(c[nt][0] + bi0, c[nt][1] + bi1);
            if (v1 < n)
                *reinterpret_cast<float2*>(outl + (size_t)v1 * 64 + cl) =
                    make_float2(c[nt][2] + bi0, c[nt][3] + bi1);
        }
    }
}

// ---------------------------------------------------------------------------
// launch: single-pass lookback scan; prescale overlapped with scan+permute;
// single gather + single gemm (chunked pipeline reverted — it regressed).
// ---------------------------------------------------------------------------
extern "C" void kernel_launch(void* const* d_in, const int* in_sizes, int n_in,
                              void* d_out, int out_size) {
    const float* x   = (const float*)d_in[0];
    const int*   ei  = (const int*)d_in[1];
    const float* Wmu = (const float*)d_in[2];
    const float* bmu = (const float*)d_in[3];
    const float* Wls = (const float*)d_in[4];
    const float* bls = (const float*)d_in[5];

    int n = in_sizes[0] / F_IN;     // 100000
    int E = in_sizes[1] / 2;        // 3200000
    const int* rowi = ei;           // edge_index[0] (src)
    const int* coli = ei + E;       // edge_index[1] (dst)

    int nb = (n + SCAN_BLK - 1) / SCAN_BLK;   // 98

    cudaStream_t s2;
    cudaStreamCreateWithFlags(&s2, cudaStreamNonBlocking);
    cudaEvent_t evFork, evJoin;
    cudaEventCreateWithFlags(&evFork, cudaEventDisableTiming);
    cudaEventCreateWithFlags(&evJoin, cudaEventDisableTiming);

    int zw_grid = ((n > 128 * 128 ? n : 128 * 128) + 255) / 256;
    k_zero_wconv<<<zw_grid, 256>>>(n, Wmu, bmu, Wls, bls);
    k_count<<<((E + 3) / 4 + 255) / 256, 256>>>(coli, E);

    // fork: prescale on s2 (needs only degree counts)
    cudaEventRecord(evFork, 0);
    cudaStreamWaitEvent(s2, evFork, 0);
    k_prescale<<<(n * F4 + 255) / 256, 256, 0, s2>>>(x, n);
    cudaEventRecord(evJoin, s2);

    // main: single-pass scan (lookback) -> permute
    k_scan<<<nb, SCAN_BLK>>>(n);
    k_permute<<<((E + 3) / 4 + 255) / 256, 256>>>(rowi, coli, E);
    cudaStreamWaitEvent(0, evJoin, 0);

    k_gather<<<(n * 32 + 255) / 256, 256>>>(n);

    int smem_bytes = 2 * 128 * 136 * (int)sizeof(__half) + 128 * (int)sizeof(float);
    cudaFuncSetAttribute(k_gemm_hmma, cudaFuncAttributeMaxDynamicSharedMemorySize,
                         smem_bytes);
    k_gemm_hmma<<<(n + 127) / 128, 256, smem_bytes>>>((float*)d_out, n);

    cudaEventDestroy(evFork);
    cudaEventDestroy(evJoin);
    cudaStreamDestroy(s2);
}

// round 16
// speedup vs baseline: 1.0400x; 1.0055x over previous
#include <cuda_runtime.h>
#include <cuda_fp16.h>
#include <stdint.h>

#define NNODES_MAX 100000
#define NROWS_PAD  100096     // padded for 128-row GEMM tiles
#define NEDGES_MAX 3200000
#define F_IN 128
#define F4 32            // float4s per feature row
#define H2_ROW 32        // uint2 (4 halves) per feature row
#define U4_ROW 16        // uint4 (8 halves) per feature row
#define SCAN_BLK 1024

// ---- scratch (static __device__ globals; allocation-free, zero-init) ----
__device__ int    g_deg[NNODES_MAX];       // in-degree counts (stable after count)
__device__ int    g_cur[NNODES_MAX];       // permute placement cursors
__device__ int    g_off[NNODES_MAX];       // CSR offsets
__device__ int    g_pub[128];              // lookback publications (0=not ready, total+1)
__device__ float  g_dinv[NNODES_MAX];
__device__ int    g_edge[NEDGES_MAX];                    // src per edge, dst-sorted
__device__ uint2  g_xh[(size_t)NNODES_MAX * H2_ROW];     // fp16(x * dinv[row])
__device__ uint2  g_acch[(size_t)NROWS_PAD * H2_ROW];    // fp16 aggregated features
__device__ __half g_wh[128 * 128];                       // combined [W_mu|W_ls] fp16, [k][j]
__device__ float  g_bias[128];                           // combined bias

// ---------------------------------------------------------------------------
// K0: zero deg + cursors + lookback flags, convert W to fp16, bias
// ---------------------------------------------------------------------------
__global__ void k_zero_wconv(int n,
                             const float* __restrict__ Wmu, const float* __restrict__ bmu,
                             const float* __restrict__ Wls, const float* __restrict__ bls) {
    int i = blockIdx.x * blockDim.x + threadIdx.x;
    if (i < n) { g_deg[i] = 0; g_cur[i] = 0; }
    if (i < 128) g_pub[i] = 0;
    if (i < 128 * 128) {
        int k = i >> 7, j = i & 127;
        float w = (j < 64) ? Wmu[k * 64 + j] : Wls[k * 64 + (j - 64)];
        g_wh[i] = __float2half_rn(w);
    }
    if (i < 128) g_bias[i] = (i < 64) ? bmu[i] : bls[i - 64];
}

// ---------------------------------------------------------------------------
// K1: in-degree count
// ---------------------------------------------------------------------------
__global__ void k_count(const int* __restrict__ col, int E) {
    int i = blockIdx.x * blockDim.x + threadIdx.x;
    int base = i * 4;
    if (base + 3 < E) {
        int4 c = *reinterpret_cast<const int4*>(col + base);
        atomicAdd(&g_deg[c.x], 1);
        atomicAdd(&g_deg[c.y], 1);
        atomicAdd(&g_deg[c.z], 1);
        atomicAdd(&g_deg[c.w], 1);
    } else if (base < E) {
        for (int e = base; e < E; ++e) atomicAdd(&g_deg[col[e]], 1);
    }
}

// ---------------------------------------------------------------------------
// K2: single-pass scan with decoupled lookback.
// ---------------------------------------------------------------------------
__global__ void k_scan(int n) {
    __shared__ int s[SCAN_BLK];
    int tid = threadIdx.x, b = blockIdx.x;
    int v = b * SCAN_BLK + tid;
    int val = (v < n) ? g_deg[v] : 0;
    s[tid] = val;
    __syncthreads();
    #pragma unroll
    for (int off = 1; off < SCAN_BLK; off <<= 1) {
        int t = (tid >= off) ? s[tid - off] : 0;
        __syncthreads();
        s[tid] += t;
        __syncthreads();
    }
    int incl = s[tid];

    if (tid == SCAN_BLK - 1) atomicExch(&g_pub[b], incl + 1);

    int part = 0;
    if (tid < b) {
        int p;
        do { p = atomicAdd(&g_pub[tid], 0); } while (p == 0);
        part = p - 1;
    }
    __syncthreads();
    s[tid] = part;
    __syncthreads();
    #pragma unroll
    for (int o = SCAN_BLK / 2; o > 0; o >>= 1) {
        if (tid < o) s[tid] += s[tid + o];
        __syncthreads();
    }
    int base = s[0];

    if (v < n) {
        g_off[v]  = base + incl - val;
        g_dinv[v] = rsqrtf((float)(val + 1));
    }
}

// ---------------------------------------------------------------------------
// K3a (side stream): prescale x into fp16 (dinv computed locally from g_deg)
// ---------------------------------------------------------------------------
__global__ void k_prescale(const float* __restrict__ x, int n) {
    int idx = blockIdx.x * blockDim.x + threadIdx.x;
    if (idx >= n * F4) return;
    int v = idx >> 5;
    float dv = rsqrtf((float)(g_deg[v] + 1));
    float4 xv = reinterpret_cast<const float4*>(x)[idx];
    __half2 h0 = __floats2half2_rn(xv.x * dv, xv.y * dv);
    __half2 h1 = __floats2half2_rn(xv.z * dv, xv.w * dv);
    uint2 o;
    o.x = *reinterpret_cast<unsigned*>(&h0);
    o.y = *reinterpret_cast<unsigned*>(&h1);
    g_xh[idx] = o;
}

// ---------------------------------------------------------------------------
// K3b (main stream): permute edges into dst-sorted order (cursors in g_cur)
// ---------------------------------------------------------------------------
__global__ void k_permute(const int* __restrict__ rowi,
                          const int* __restrict__ coli, int E) {
    int i = blockIdx.x * blockDim.x + threadIdx.x;
    int base = i * 4;
    if (base + 3 < E) {
        int4 s4 = *reinterpret_cast<const int4*>(rowi + base);
        int4 d4 = *reinterpret_cast<const int4*>(coli + base);
        g_edge[g_off[d4.x] + atomicAdd(&g_cur[d4.x], 1)] = s4.x;
        g_edge[g_off[d4.y] + atomicAdd(&g_cur[d4.y], 1)] = s4.y;
        g_edge[g_off[d4.z] + atomicAdd(&g_cur[d4.z], 1)] = s4.z;
        g_edge[g_off[d4.w] + atomicAdd(&g_cur[d4.w], 1)] = s4.w;
    } else if (base < E) {
        for (int e = base; e < E; ++e) {
            int s = rowi[e], d = coli[e];
            g_edge[g_off[d] + atomicAdd(&g_cur[d], 1)] = s;
        }
    }
}

// ---------------------------------------------------------------------------
// K4: gather-aggregate, HALF-WARP layout.
// One warp per dst node; half-warp h covers the full 256B row of edge (e+h)
// with LDG.128 (16B/lane). One LDG instruction = 512B = 2 edges. Final
// shfl_xor(16) merges the two half-warp partials. fp32 accumulate.
// ---------------------------------------------------------------------------
__global__ void k_gather(int n) {
    int gwarp = (blockIdx.x * blockDim.x + threadIdx.x) >> 5;
    int lane  = threadIdx.x & 31;
    if (gwarp >= n) return;
    int v    = gwarp;
    int half = lane >> 4;        // 0 or 1
    int sub  = lane & 15;        // 16B chunk index within row

    float dv_dst = g_dinv[v];
    int offs = g_off[v];
    int cnt  = g_deg[v];

    const uint4* x4 = reinterpret_cast<const uint4*>(g_xh);

    float acc[8];
    // self-loop: half 0 loads its chunk; half 1 starts at zero
    if (half == 0) {
        uint4 h = __ldg(x4 + (size_t)v * U4_ROW + sub);
        float2 f0 = __half22float2(*reinterpret_cast<__half2*>(&h.x));
        float2 f1 = __half22float2(*reinterpret_cast<__half2*>(&h.y));
        float2 f2 = __half22float2(*reinterpret_cast<__half2*>(&h.z));
        float2 f3 = __half22float2(*reinterpret_cast<__half2*>(&h.w));
        acc[0] = f0.x; acc[1] = f0.y; acc[2] = f1.x; acc[3] = f1.y;
        acc[4] = f2.x; acc[5] = f2.y; acc[6] = f3.x; acc[7] = f3.y;
    } else {
        #pragma unroll
        for (int q = 0; q < 8; ++q) acc[q] = 0.f;
    }

    for (int base = 0; base < cnt; base += 32) {
        int m = min(32, cnt - base);
        int s = 0;
        if (base + lane < cnt) s = __ldg(&g_edge[offs + base + lane]);

        int e = 0;
        // 2 LDG.128 per iteration = 4 edges in flight
        for (; e + 3 < m; e += 4) {
            int sA = __shfl_sync(0xffffffffu, s, e + half);
            int sB = __shfl_sync(0xffffffffu, s, e + 2 + half);
            uint4 hA = __ldg(x4 + (size_t)sA * U4_ROW + sub);
            uint4 hB = __ldg(x4 + (size_t)sB * U4_ROW + sub);
            float2 f;
            f = __half22float2(*reinterpret_cast<__half2*>(&hA.x)); acc[0] += f.x; acc[1] += f.y;
            f = __half22float2(*reinterpret_cast<__half2*>(&hA.y)); acc[2] += f.x; acc[3] += f.y;
            f = __half22float2(*reinterpret_cast<__half2*>(&hA.z)); acc[4] += f.x; acc[5] += f.y;
            f = __half22float2(*reinterpret_cast<__half2*>(&hA.w)); acc[6] += f.x; acc[7] += f.y;
            f = __half22float2(*reinterpret_cast<__half2*>(&hB.x)); acc[0] += f.x; acc[1] += f.y;
            f = __half22float2(*reinterpret_cast<__half2*>(&hB.y)); acc[2] += f.x; acc[3] += f.y;
            f = __half22float2(*reinterpret_cast<__half2*>(&hB.z)); acc[4] += f.x; acc[5] += f.y;
            f = __half22float2(*reinterpret_cast<__half2*>(&hB.w)); acc[6] += f.x; acc[7] += f.y;
        }
        // one pair (2 edges)
        for (; e + 1 < m; e += 2) {
            int sA = __shfl_sync(0xffffffffu, s, e + half);
            uint4 hA = __ldg(x4 + (size_t)sA * U4_ROW + sub);
            float2 f;
            f = __half22float2(*reinterpret_cast<__half2*>(&hA.x)); acc[0] += f.x; acc[1] += f.y;
            f = __half22float2(*reinterpret_cast<__half2*>(&hA.y)); acc[2] += f.x; acc[3] += f.y;
            f = __half22float2(*reinterpret_cast<__half2*>(&hA.z)); acc[4] += f.x; acc[5] += f.y;
            f = __half22float2(*reinterpret_cast<__half2*>(&hA.w)); acc[6] += f.x; acc[7] += f.y;
        }
        // single tail edge (half 0 only)
        if (e < m) {
            int sA = __shfl_sync(0xffffffffu, s, e);
            if (half == 0) {
                uint4 hA = __ldg(x4 + (size_t)sA * U4_ROW + sub);
                float2 f;
                f = __half22float2(*reinterpret_cast<__half2*>(&hA.x)); acc[0] += f.x; acc[1] += f.y;
                f = __half22float2(*reinterpret_cast<__half2*>(&hA.y)); acc[2] += f.x; acc[3] += f.y;
                f = __half22float2(*reinterpret_cast<__half2*>(&hA.z)); acc[4] += f.x; acc[5] += f.y;
                f = __half22float2(*reinterpret_cast<__half2*>(&hA.w)); acc[6] += f.x; acc[7] += f.y;
            }
        }
    }

    // merge half-warp partials: lane L += lane L+16
    #pragma unroll
    for (int q = 0; q < 8; ++q)
        acc[q] += __shfl_xor_sync(0xffffffffu, acc[q], 16);

    if (half == 0) {
        __half2 h0 = __floats2half2_rn(acc[0] * dv_dst, acc[1] * dv_dst);
        __half2 h1 = __floats2half2_rn(acc[2] * dv_dst, acc[3] * dv_dst);
        __half2 h2 = __floats2half2_rn(acc[4] * dv_dst, acc[5] * dv_dst);
        __half2 h3 = __floats2half2_rn(acc[6] * dv_dst, acc[7] * dv_dst);
        uint4 o;
        o.x = *reinterpret_cast<unsigned*>(&h0);
        o.y = *reinterpret_cast<unsigned*>(&h1);
        o.z = *reinterpret_cast<unsigned*>(&h2);
        o.w = *reinterpret_cast<unsigned*>(&h3);
        reinterpret_cast<uint4*>(g_acch)[(size_t)v * U4_ROW + sub] = o;
    }
}

// ---------------------------------------------------------------------------
// K5: HMMA GEMM:  out = g_acch @ g_wh + g_bias   (fp16 in, fp32 accumulate)
// ---------------------------------------------------------------------------
__global__ void k_gemm_hmma(float* __restrict__ out, int n) {
    extern __shared__ __half sm[];
    __half* As = sm;                         // 128*136
    __half* Ws = sm + 128 * 136;             // 128*136
    float*  bs = (float*)(sm + 2 * 128 * 136);

    int tid = threadIdx.x;
    int rowbase = blockIdx.x * 128;

    {
        const uint4* src = reinterpret_cast<const uint4*>(g_wh);
        for (int t = tid; t < 128 * 16; t += 256) {
            int r = t >> 4, c = t & 15;
            *reinterpret_cast<uint4*>(Ws + r * 136 + c * 8) = src[r * 16 + c];
        }
    }
    {
        const uint4* src = reinterpret_cast<const uint4*>(g_acch);
        for (int t = tid; t < 128 * 16; t += 256) {
            int r = t >> 4, c = t & 15;
            *reinterpret_cast<uint4*>(As + r * 136 + c * 8) =
                src[(size_t)(rowbase + r) * 16 + c];
        }
    }
    if (tid < 128) bs[tid] = g_bias[tid];
    __syncthreads();

    int warp = tid >> 5, lane = tid & 31;
    int m0 = warp * 16;

    float c[16][4];
    #pragma unroll
    for (int t = 0; t < 16; ++t) { c[t][0] = c[t][1] = c[t][2] = c[t][3] = 0.f; }

    uint32_t a_base = (uint32_t)__cvta_generic_to_shared(As);
    uint32_t b_base = (uint32_t)__cvta_generic_to_shared(Ws);

    #pragma unroll
    for (int kk = 0; kk < 8; ++kk) {
        int k0 = kk * 16;
        uint32_t a0, a1, a2, a3;
        {
            int r   = m0 + (lane & 15);
            int col = k0 + 8 * (lane >> 4);
            uint32_t addr = a_base + (uint32_t)(r * 136 + col) * 2u;
            asm volatile(
                "ldmatrix.sync.aligned.m8n8.x4.shared.b16 {%0,%1,%2,%3}, [%4];"
                : "=r"(a0), "=r"(a1), "=r"(a2), "=r"(a3) : "r"(addr));
        }
        #pragma unroll
        for (int nt = 0; nt < 16; ++nt) {
            uint32_t b0, b1;
            int r = k0 + (lane & 15);
            uint32_t addr = b_base + (uint32_t)(r * 136 + nt * 8) * 2u;
            asm volatile(
                "ldmatrix.sync.aligned.m8n8.x2.trans.shared.b16 {%0,%1}, [%2];"
                : "=r"(b0), "=r"(b1) : "r"(addr));
            asm volatile(
                "mma.sync.aligned.m16n8k16.row.col.f32.f16.f16.f32 "
                "{%0,%1,%2,%3}, {%4,%5,%6,%7}, {%8,%9}, {%0,%1,%2,%3};"
                : "+f"(c[nt][0]), "+f"(c[nt][1]), "+f"(c[nt][2]), "+f"(c[nt][3])
                : "r"(a0), "r"(a1), "r"(a2), "r"(a3), "r"(b0), "r"(b1));
        }
    }

    int g  = lane >> 2;
    int t4 = lane & 3;
    float* outm = out;
    float* outl = out + (size_t)n * 64;
    #pragma unroll
    for (int nt = 0; nt < 16; ++nt) {
        int col = nt * 8 + t4 * 2;
        float bi0 = bs[col], bi1 = bs[col + 1];
        int v0 = rowbase + m0 + g;
        int v1 = v0 + 8;
        if (col < 64) {
            if (v0 < n)
                *reinterpret_cast<float2*>(outm + (size_t)v0 * 64 + col) =
                    make_float2(c[nt][0] + bi0, c[nt][1] + bi1);
            if (v1 < n)
                *reinterpret_cast<float2*>(outm + (size_t)v1 * 64 + col) =
                    make_float2(c[nt][2] + bi0, c[nt][3] + bi1);
        } else {
            int cl = col - 64;
            if (v0 < n)
                *reinterpret_cast<float2*>(outl + (size_t)v0 * 64 + cl) =
                    make_float2(c[nt][0] + bi0, c[nt][1] + bi1);
            if (v1 < n)
                *reinterpret_cast<float2*>(outl + (size_t)v1 * 64 + cl) =
                    make_float2(c[nt][2] + bi0, c[nt][3] + bi1);
        }
    }
}

// ---------------------------------------------------------------------------
// launch (structure identical to the 180.3us best)
// ---------------------------------------------------------------------------
extern "C" void kernel_launch(void* const* d_in, const int* in_sizes, int n_in,
                              void* d_out, int out_size) {
    const float* x   = (const float*)d_in[0];
    const int*   ei  = (const int*)d_in[1];
    const float* Wmu = (const float*)d_in[2];
    const float* bmu = (const float*)d_in[3];
    const float* Wls = (const float*)d_in[4];
    const float* bls = (const float*)d_in[5];

    int n = in_sizes[0] / F_IN;     // 100000
    int E = in_sizes[1] / 2;        // 3200000
    const int* rowi = ei;           // edge_index[0] (src)
    const int* coli = ei + E;       // edge_index[1] (dst)

    int nb = (n + SCAN_BLK - 1) / SCAN_BLK;   // 98

    cudaStream_t s2;
    cudaStreamCreateWithFlags(&s2, cudaStreamNonBlocking);
    cudaEvent_t evFork, evJoin;
    cudaEventCreateWithFlags(&evFork, cudaEventDisableTiming);
    cudaEventCreateWithFlags(&evJoin, cudaEventDisableTiming);

    int zw_grid = ((n > 128 * 128 ? n : 128 * 128) + 255) / 256;
    k_zero_wconv<<<zw_grid, 256>>>(n, Wmu, bmu, Wls, bls);
    k_count<<<((E + 3) / 4 + 255) / 256, 256>>>(coli, E);

    cudaEventRecord(evFork, 0);
    cudaStreamWaitEvent(s2, evFork, 0);
    k_prescale<<<(n * F4 + 255) / 256, 256, 0, s2>>>(x, n);
    cudaEventRecord(evJoin, s2);

    k_scan<<<nb, SCAN_BLK>>>(n);
    k_permute<<<((E + 3) / 4 + 255) / 256, 256>>>(rowi, coli, E);
    cudaStreamWaitEvent(0, evJoin, 0);

    k_gather<<<(n * 32 + 255) / 256, 256>>>(n);

    int smem_bytes = 2 * 128 * 136 * (int)sizeof(__half) + 128 * (int)sizeof(float);
    cudaFuncSetAttribute(k_gemm_hmma, cudaFuncAttributeMaxDynamicSharedMemorySize,
                         smem_bytes);
    k_gemm_hmma<<<(n + 127) / 128, 256, smem_bytes>>>((float*)d_out, n);

    cudaEventDestroy(evFork);
    cudaEventDestroy(evJoin);
    cudaStreamDestroy(s2);
}